// round 6
// baseline (speedup 1.0000x reference)
#include <cuda_runtime.h>
#include <math.h>

#define BATCH 64
#define HID   1024
#define INP   1024
#define SPLITK 8

typedef unsigned long long u64;

// ---------------- scratch (static device globals; no allocation) -------------
__device__ float g_part[SPLITK][6][BATCH][HID];  // split-K GEMM partials
__device__ float g_f [BATCH][HID];               // sigmoid(f_tilda)
__device__ float g_a [BATCH][HID];               // i_prime * v
__device__ float g_o [BATCH][HID];               // sigmoid(o_tilda)
__device__ float g_k [BATCH][HID];               // k_t (scaled by 1/32)
__device__ float g_q [BATCH][HID];               // q_t
__device__ float g_nq[BATCH];                    // sum_j n_t * q_t

struct WPtrs {
    const float* W[6];
    const float* b[6];
};

// ---------------- kernel 1: six fused GEMMs, split-K=8, f32x2 FMA ------------
// out_part[z][g][m][n] = sum_{k in chunk z} x[m][k] * W_g[n][k]
// BM=64 (all batch), BN=64, BK=32, 256 threads, 4x4 microtile per thread,
// computed as 4 rows x 2 column-pairs with packed fma.rn.f32x2.
__global__ void __launch_bounds__(256) gemm6_kernel(const float* __restrict__ x, WPtrs wp)
{
    const int ntile = blockIdx.x;   // 0..15
    const int g     = blockIdx.y;   // 0..5
    const int z     = blockIdx.z;   // 0..7
    const float* __restrict__ W = wp.W[g];

    __shared__ float xs2[32][132];  // [kk][2*m] duplicated pairs, padded
    __shared__ float ws [32][68];   // [kk][n], padded

    const int tid = threadIdx.x;
    const int ty  = tid >> 4;       // 0..15  (m groups of 4)
    const int tx  = tid & 15;       // 0..15  (n groups of 4)
    const int n0  = ntile * 64;

    u64 acc01[4], acc23[4];
#pragma unroll
    for (int i = 0; i < 4; ++i) { acc01[i] = 0ULL; acc23[i] = 0ULL; }

    for (int kt = 0; kt < 4; ++kt) {
        const int k0 = z * 128 + kt * 32;
        // load 64x32 tiles of x (duplicated) and W (transposed into smem)
#pragma unroll
        for (int i = 0; i < 2; ++i) {
            int f  = tid + i * 256;       // 0..511 -> 512 float4 per tile
            int m  = f >> 3;              // 0..63
            int kc = (f & 7) * 4;         // 0,4,...,28
            float4 xv = *(const float4*)(x + (size_t)m * INP + k0 + kc);
            xs2[kc + 0][2*m] = xv.x; xs2[kc + 0][2*m+1] = xv.x;
            xs2[kc + 1][2*m] = xv.y; xs2[kc + 1][2*m+1] = xv.y;
            xs2[kc + 2][2*m] = xv.z; xs2[kc + 2][2*m+1] = xv.z;
            xs2[kc + 3][2*m] = xv.w; xs2[kc + 3][2*m+1] = xv.w;
            float4 wv = *(const float4*)(W + (size_t)(n0 + m) * INP + k0 + kc);
            ws[kc + 0][m] = wv.x; ws[kc + 1][m] = wv.y;
            ws[kc + 2][m] = wv.z; ws[kc + 3][m] = wv.w;
        }
        __syncthreads();
#pragma unroll
        for (int kk = 0; kk < 32; ++kk) {
            u64 b01 = *(const u64*)&ws[kk][tx * 4];
            u64 b23 = *(const u64*)&ws[kk][tx * 4 + 2];
#pragma unroll
            for (int i = 0; i < 4; ++i) {
                u64 aa = *(const u64*)&xs2[kk][(ty * 4 + i) * 2];
                asm("fma.rn.f32x2 %0, %1, %2, %0;" : "+l"(acc01[i]) : "l"(aa), "l"(b01));
                asm("fma.rn.f32x2 %0, %1, %2, %0;" : "+l"(acc23[i]) : "l"(aa), "l"(b23));
            }
        }
        __syncthreads();
    }

    float* out = &g_part[z][g][0][0];
#pragma unroll
    for (int i = 0; i < 4; ++i) {
        int m = ty * 4 + i;
        // packed lanes are (col, col+1) little-endian -> direct 8B stores
        *(u64*)&out[(size_t)m * HID + n0 + tx * 4]     = acc01[i];
        *(u64*)&out[(size_t)m * HID + n0 + tx * 4 + 2] = acc23[i];
    }
}

// ---------------- kernel 2: gate pointwise + per-batch reduction -------------
__global__ void __launch_bounds__(256) pointwise_kernel(
    const float* __restrict__ nprev, const float* __restrict__ mprev_in,
    WPtrs wp, float* __restrict__ out_n, float* __restrict__ out_m)
{
    const int b   = blockIdx.x;
    const int tid = threadIdx.x;
    float local_nq = 0.0f;

#pragma unroll
    for (int t = 0; t < 4; ++t) {
        const int h = tid + t * 256;
        float s[6];
#pragma unroll
        for (int g = 0; g < 6; ++g) {
            float v = wp.b[g][h];
#pragma unroll
            for (int zz = 0; zz < SPLITK; ++zz) v += g_part[zz][g][b][h];
            s[g] = v;
        }
        const float it   = s[0];
        const float ftil = s[1];
        const float otil = s[2];
        const float qv   = s[3];
        const float kv   = s[4] * (1.0f / 32.0f);   // / sqrt(1024)
        const float vv   = s[5];

        const float ft   = 1.0f / (1.0f + expf(-ftil));
        // log(sigmoid(ftil)), numerically stable
        const float lgf  = (ftil >= 0.0f) ? -log1pf(expf(-ftil))
                                          : (ftil - log1pf(expf(ftil)));
        const float mp = mprev_in[(size_t)b * HID + h];
        const float mt = fmaxf(lgf + mp, it);
        const float ip = expf(it - mt);
        const float nt = ft * nprev[(size_t)b * HID + h] + ip * kv;

        out_n[(size_t)b * HID + h] = nt;
        out_m[(size_t)b * HID + h] = mt;
        g_f[b][h] = ft;
        g_a[b][h] = ip * vv;
        g_o[b][h] = 1.0f / (1.0f + expf(-otil));
        g_k[b][h] = kv;
        g_q[b][h] = qv;
        local_nq += nt * qv;
    }

    // block reduce local_nq (256 threads = 8 warps)
    __shared__ float red[8];
#pragma unroll
    for (int off = 16; off > 0; off >>= 1)
        local_nq += __shfl_xor_sync(0xFFFFFFFFu, local_nq, off);
    if ((tid & 31) == 0) red[tid >> 5] = local_nq;
    __syncthreads();
    if (tid < 8) {
        float v = red[tid];
#pragma unroll
        for (int off = 4; off > 0; off >>= 1)
            v += __shfl_xor_sync(0xFFu, v, off);
        if (tid == 0) g_nq[b] = v;
    }
}

// ---------------- kernel 3: fused fast-weight update + readout ---------------
// One warp per C row; 16 rows per block; k,q cached in smem per block.
// C stream uses evict-streaming (ldcs/stcs) — data has no reuse.
__global__ void __launch_bounds__(512) update_kernel(
    const float* __restrict__ C, float* __restrict__ outC, float* __restrict__ outH)
{
    __shared__ float sk[HID];
    __shared__ float sq[HID];

    const int b  = blockIdx.x >> 6;          // 64 blocks per batch
    const int r0 = (blockIdx.x & 63) << 4;   // 16 rows per block

    for (int i = threadIdx.x; i < HID; i += 512) {
        sk[i] = g_k[b][i];
        sq[i] = g_q[b][i];
    }
    __syncthreads();

    const int w    = threadIdx.x >> 5;
    const int lane = threadIdx.x & 31;
    const int r    = r0 + w;

    const float f = g_f[b][r];
    const float a = g_a[b][r];

    const size_t base = ((size_t)b * HID + r) * HID;
    const float4* __restrict__ Crow = (const float4*)(C + base);
    float4* __restrict__ Orow       = (float4*)(outC + base);
    const float4* __restrict__ k4p  = (const float4*)sk;
    const float4* __restrict__ q4p  = (const float4*)sq;

    float acc = 0.0f;
#pragma unroll
    for (int t = 0; t < 8; ++t) {
        const int j  = lane + t * 32;        // float4 index, coalesced
        float4 c  = __ldcs(Crow + j);
        float4 k4 = k4p[j];
        float4 q4 = q4p[j];
        float4 ct;
        ct.x = fmaf(f, c.x, a * k4.x);
        ct.y = fmaf(f, c.y, a * k4.y);
        ct.z = fmaf(f, c.z, a * k4.z);
        ct.w = fmaf(f, c.w, a * k4.w);
        __stcs(Orow + j, ct);
        acc = fmaf(ct.x, q4.x, acc);
        acc = fmaf(ct.y, q4.y, acc);
        acc = fmaf(ct.z, q4.z, acc);
        acc = fmaf(ct.w, q4.w, acc);
    }
#pragma unroll
    for (int off = 16; off > 0; off >>= 1)
        acc += __shfl_xor_sync(0xFFFFFFFFu, acc, off);

    if (lane == 0) {
        const float div = fmaxf(fabsf(g_nq[b]), 1.0f);
        outH[(size_t)b * HID + r] = g_o[b][r] * acc / div;
    }
}

// ---------------- launch ------------------------------------------------------
extern "C" void kernel_launch(void* const* d_in, const int* in_sizes, int n_in,
                              void* d_out, int out_size)
{
    const float* x     = (const float*)d_in[0];
    const float* Cin   = (const float*)d_in[1];
    const float* nprev = (const float*)d_in[2];
    const float* mprev = (const float*)d_in[3];

    WPtrs wp;
    for (int g = 0; g < 6; ++g) {
        wp.W[g] = (const float*)d_in[4 + 2 * g];
        wp.b[g] = (const float*)d_in[5 + 2 * g];
    }

    float* out  = (float*)d_out;
    float* outH = out;                                       // (64,1024)
    float* outC = out + (size_t)BATCH * HID;                 // (64,1024,1024)
    float* outN = outC + (size_t)BATCH * HID * HID;          // (64,1024)
    float* outM = outN + (size_t)BATCH * HID;                // (64,1024)

    gemm6_kernel<<<dim3(16, 6, SPLITK), 256>>>(x, wp);
    pointwise_kernel<<<BATCH, 256>>>(nprev, mprev, wp, outN, outM);
    update_kernel<<<BATCH * (HID / 16), 512>>>(Cin, outC, outH);
}

// round 8
// speedup vs baseline: 1.0636x; 1.0636x over previous
#include <cuda_runtime.h>
#include <math.h>

#define BATCH 64
#define HID   1024
#define INP   1024
#define SPLITK 8

// ---------------- scratch (static device globals; no allocation) -------------
__device__ float g_part[SPLITK][6][BATCH][HID];  // split-K GEMM partials
__device__ float g_f [BATCH][HID];               // sigmoid(f_tilda)
__device__ float g_a [BATCH][HID];               // i_prime * v
__device__ float g_o [BATCH][HID];               // sigmoid(o_tilda)
__device__ float g_k [BATCH][HID];               // k_t (scaled by 1/32)
__device__ float g_q [BATCH][HID];               // q_t
__device__ float g_nq[BATCH];                    // sum_j n_t * q_t

struct WPtrs {
    const float* W[6];
    const float* b[6];
};

// ---------------- kernel 1: six fused GEMMs, split-K=8 -----------------------
// out_part[z][g][m][n] = sum_{k in chunk z} x[m][k] * W_g[n][k]
// BM=64 (all batch), BN=64, BK=32, 128 threads, 4x8 microtile per thread.
__global__ void __launch_bounds__(128) gemm6_kernel(const float* __restrict__ x, WPtrs wp)
{
    const int ntile = blockIdx.x;   // 0..15
    const int g     = blockIdx.y;   // 0..5
    const int z     = blockIdx.z;   // 0..7
    const float* __restrict__ W = wp.W[g];

    __shared__ float xs[32][68];    // [kk][m], padded
    __shared__ float ws[32][68];    // [kk][n], padded

    const int tid = threadIdx.x;
    const int tx  = tid & 15;       // 0..15  (m groups of 4)
    const int ty  = tid >> 4;       // 0..7   (n groups of 8)
    const int n0  = ntile * 64;

    float acc[4][8];
#pragma unroll
    for (int i = 0; i < 4; ++i)
#pragma unroll
        for (int j = 0; j < 8; ++j) acc[i][j] = 0.0f;

    for (int kt = 0; kt < 4; ++kt) {
        const int k0 = z * 128 + kt * 32;
        // load 64x32 tiles of x and W (transposed into smem); 4 float4 each
#pragma unroll
        for (int i = 0; i < 4; ++i) {
            int f  = tid + i * 128;       // 0..511 -> 512 float4 per tile
            int m  = f >> 3;              // 0..63
            int kc = (f & 7) * 4;         // 0,4,...,28
            float4 xv = *(const float4*)(x + (size_t)m * INP + k0 + kc);
            xs[kc + 0][m] = xv.x; xs[kc + 1][m] = xv.y;
            xs[kc + 2][m] = xv.z; xs[kc + 3][m] = xv.w;
            float4 wv = *(const float4*)(W + (size_t)(n0 + m) * INP + k0 + kc);
            ws[kc + 0][m] = wv.x; ws[kc + 1][m] = wv.y;
            ws[kc + 2][m] = wv.z; ws[kc + 3][m] = wv.w;
        }
        __syncthreads();
#pragma unroll
        for (int kk = 0; kk < 32; ++kk) {
            float4 av  = *(const float4*)&xs[kk][tx * 4];
            float4 bv0 = *(const float4*)&ws[kk][ty * 8];
            float4 bv1 = *(const float4*)&ws[kk][ty * 8 + 4];
            float a4[4] = {av.x, av.y, av.z, av.w};
            float b8[8] = {bv0.x, bv0.y, bv0.z, bv0.w, bv1.x, bv1.y, bv1.z, bv1.w};
#pragma unroll
            for (int i = 0; i < 4; ++i)
#pragma unroll
                for (int j = 0; j < 8; ++j)
                    acc[i][j] = fmaf(a4[i], b8[j], acc[i][j]);
        }
        __syncthreads();
    }

    float* out = &g_part[z][g][0][0];
#pragma unroll
    for (int i = 0; i < 4; ++i) {
        int m = tx * 4 + i;
        float4 v0 = make_float4(acc[i][0], acc[i][1], acc[i][2], acc[i][3]);
        float4 v1 = make_float4(acc[i][4], acc[i][5], acc[i][6], acc[i][7]);
        *(float4*)&out[(size_t)m * HID + n0 + ty * 8]     = v0;
        *(float4*)&out[(size_t)m * HID + n0 + ty * 8 + 4] = v1;
    }
}

// ---------------- kernel 2: gate pointwise + per-batch reduction -------------
__global__ void __launch_bounds__(256) pointwise_kernel(
    const float* __restrict__ nprev, const float* __restrict__ mprev_in,
    WPtrs wp, float* __restrict__ out_n, float* __restrict__ out_m)
{
    const int b   = blockIdx.x;
    const int tid = threadIdx.x;
    float local_nq = 0.0f;

#pragma unroll
    for (int t = 0; t < 4; ++t) {
        const int h = tid + t * 256;
        float s[6];
#pragma unroll
        for (int g = 0; g < 6; ++g) {
            float v = wp.b[g][h];
#pragma unroll
            for (int zz = 0; zz < SPLITK; ++zz) v += g_part[zz][g][b][h];
            s[g] = v;
        }
        const float it   = s[0];
        const float ftil = s[1];
        const float otil = s[2];
        const float qv   = s[3];
        const float kv   = s[4] * (1.0f / 32.0f);   // / sqrt(1024)
        const float vv   = s[5];

        const float ft   = 1.0f / (1.0f + expf(-ftil));
        // log(sigmoid(ftil)), numerically stable
        const float lgf  = (ftil >= 0.0f) ? -log1pf(expf(-ftil))
                                          : (ftil - log1pf(expf(ftil)));
        const float mp = mprev_in[(size_t)b * HID + h];
        const float mt = fmaxf(lgf + mp, it);
        const float ip = expf(it - mt);
        const float nt = ft * nprev[(size_t)b * HID + h] + ip * kv;

        out_n[(size_t)b * HID + h] = nt;
        out_m[(size_t)b * HID + h] = mt;
        g_f[b][h] = ft;
        g_a[b][h] = ip * vv;
        g_o[b][h] = 1.0f / (1.0f + expf(-otil));
        g_k[b][h] = kv;
        g_q[b][h] = qv;
        local_nq += nt * qv;
    }

    // block reduce local_nq (256 threads = 8 warps)
    __shared__ float red[8];
#pragma unroll
    for (int off = 16; off > 0; off >>= 1)
        local_nq += __shfl_xor_sync(0xFFFFFFFFu, local_nq, off);
    if ((tid & 31) == 0) red[tid >> 5] = local_nq;
    __syncthreads();
    if (tid < 8) {
        float v = red[tid];
#pragma unroll
        for (int off = 4; off > 0; off >>= 1)
            v += __shfl_xor_sync(0xFFu, v, off);
        if (tid == 0) g_nq[b] = v;
    }
}

// ---------------- kernel 3: fused fast-weight update + readout ---------------
// One warp per C row; 16 rows per block; k,q cached in smem per block.
__global__ void __launch_bounds__(512) update_kernel(
    const float* __restrict__ C, float* __restrict__ outC, float* __restrict__ outH)
{
    __shared__ float sk[HID];
    __shared__ float sq[HID];

    const int b  = blockIdx.x >> 6;          // 64 blocks per batch
    const int r0 = (blockIdx.x & 63) << 4;   // 16 rows per block

    for (int i = threadIdx.x; i < HID; i += 512) {
        sk[i] = g_k[b][i];
        sq[i] = g_q[b][i];
    }
    __syncthreads();

    const int w    = threadIdx.x >> 5;
    const int lane = threadIdx.x & 31;
    const int r    = r0 + w;

    const float f = g_f[b][r];
    const float a = g_a[b][r];

    const size_t base = ((size_t)b * HID + r) * HID;
    const float4* __restrict__ Crow = (const float4*)(C + base);
    float4* __restrict__ Orow       = (float4*)(outC + base);
    const float4* __restrict__ k4p  = (const float4*)sk;
    const float4* __restrict__ q4p  = (const float4*)sq;

    float acc = 0.0f;
#pragma unroll
    for (int t = 0; t < 8; ++t) {
        const int j  = lane + t * 32;        // float4 index, coalesced
        float4 c  = Crow[j];
        float4 k4 = k4p[j];
        float4 q4 = q4p[j];
        float4 ct;
        ct.x = fmaf(f, c.x, a * k4.x);
        ct.y = fmaf(f, c.y, a * k4.y);
        ct.z = fmaf(f, c.z, a * k4.z);
        ct.w = fmaf(f, c.w, a * k4.w);
        Orow[j] = ct;
        acc = fmaf(ct.x, q4.x, acc);
        acc = fmaf(ct.y, q4.y, acc);
        acc = fmaf(ct.z, q4.z, acc);
        acc = fmaf(ct.w, q4.w, acc);
    }
#pragma unroll
    for (int off = 16; off > 0; off >>= 1)
        acc += __shfl_xor_sync(0xFFFFFFFFu, acc, off);

    if (lane == 0) {
        const float div = fmaxf(fabsf(g_nq[b]), 1.0f);
        outH[(size_t)b * HID + r] = g_o[b][r] * acc / div;
    }
}

// ---------------- launch ------------------------------------------------------
extern "C" void kernel_launch(void* const* d_in, const int* in_sizes, int n_in,
                              void* d_out, int out_size)
{
    const float* x     = (const float*)d_in[0];
    const float* Cin   = (const float*)d_in[1];
    const float* nprev = (const float*)d_in[2];
    const float* mprev = (const float*)d_in[3];

    WPtrs wp;
    for (int g = 0; g < 6; ++g) {
        wp.W[g] = (const float*)d_in[4 + 2 * g];
        wp.b[g] = (const float*)d_in[5 + 2 * g];
    }

    float* out  = (float*)d_out;
    float* outH = out;                                       // (64,1024)
    float* outC = out + (size_t)BATCH * HID;                 // (64,1024,1024)
    float* outN = outC + (size_t)BATCH * HID * HID;          // (64,1024)
    float* outM = outN + (size_t)BATCH * HID;                // (64,1024)

    gemm6_kernel<<<dim3(16, 6, SPLITK), 128>>>(x, wp);
    pointwise_kernel<<<BATCH, 256>>>(nprev, mprev, wp, outN, outM);
    update_kernel<<<BATCH * (HID / 16), 512>>>(Cin, outC, outH);
}

// round 11
// speedup vs baseline: 1.1493x; 1.0806x over previous
#include <cuda_runtime.h>
#include <math.h>

#define BATCH 64
#define HID   1024
#define INP   1024
#define SPLITK 8

// ---------------- scratch (static device globals; no allocation) -------------
__device__ float g_part[SPLITK][6][BATCH][HID];  // split-K GEMM partials
__device__ float g_f [BATCH][HID];               // sigmoid(f_tilda)
__device__ float g_a [BATCH][HID];               // i_prime * v
__device__ float g_o [BATCH][HID];               // sigmoid(o_tilda)
__device__ float g_k [BATCH][HID];               // k_t (scaled by 1/32)
__device__ float g_q [BATCH][HID];               // q_t
__device__ float g_nq[BATCH];                    // sum_j n_t * q_t

struct WPtrs {
    const float* W[6];
    const float* b[6];
};

// ---------------- kernel 1: six fused GEMMs, split-K=8, pipelined ------------
// out_part[z][g][m][n] = sum_{k in chunk z} x[m][k] * W_g[n][k]
// BM=64 (all batch), BN=64, BK=32, 256 threads, 4x4 microtile per thread.
// 2-stage smem ping-pong + register double-buffer: LDG for tile kt+1 issued
// before computing tile kt; one __syncthreads per iteration.
__global__ void __launch_bounds__(256, 3) gemm6_kernel(const float* __restrict__ x, WPtrs wp)
{
    const int ntile = blockIdx.x;   // 0..15
    const int g     = blockIdx.y;   // 0..5
    const int z     = blockIdx.z;   // 0..7
    const float* __restrict__ W = wp.W[g];

    __shared__ float xs[2][32][68];  // [buf][kk][m], padded
    __shared__ float ws[2][32][68];  // [buf][kk][n], padded

    const int tid = threadIdx.x;
    const int ty  = tid >> 4;        // 0..15 (m groups of 4)
    const int tx  = tid & 15;        // 0..15 (n groups of 4)
    const int n0  = ntile * 64;
    const int lm  = tid >> 3;        // 0..31 (load row, +32 for second half)
    const int lk  = (tid & 7) * 4;   // 0,4,...,28

    float4 xr[2], wr[2];

#define LDG_TILE(k0)                                                          \
    {                                                                          \
        _Pragma("unroll")                                                      \
        for (int i = 0; i < 2; ++i) {                                          \
            int m = lm + i * 32;                                               \
            xr[i] = *(const float4*)(x + (size_t)m * INP + (k0) + lk);         \
            wr[i] = *(const float4*)(W + (size_t)(n0 + m) * INP + (k0) + lk);  \
        }                                                                      \
    }

#define STS_TILE(buf)                                                          \
    {                                                                          \
        _Pragma("unroll")                                                      \
        for (int i = 0; i < 2; ++i) {                                          \
            int m = lm + i * 32;                                               \
            xs[buf][lk + 0][m] = xr[i].x; xs[buf][lk + 1][m] = xr[i].y;        \
            xs[buf][lk + 2][m] = xr[i].z; xs[buf][lk + 3][m] = xr[i].w;        \
            ws[buf][lk + 0][m] = wr[i].x; ws[buf][lk + 1][m] = wr[i].y;        \
            ws[buf][lk + 2][m] = wr[i].z; ws[buf][lk + 3][m] = wr[i].w;        \
        }                                                                      \
    }

    const int kbase = z * 128;

    LDG_TILE(kbase);
    STS_TILE(0);
    __syncthreads();

    float acc[4][4];
#pragma unroll
    for (int i = 0; i < 4; ++i)
#pragma unroll
        for (int j = 0; j < 4; ++j) acc[i][j] = 0.0f;

#pragma unroll
    for (int kt = 0; kt < 4; ++kt) {
        const int cur = kt & 1;
        if (kt < 3) LDG_TILE(kbase + (kt + 1) * 32);
#pragma unroll
        for (int kk = 0; kk < 32; ++kk) {
            float4 av = *(const float4*)&xs[cur][kk][ty * 4];
            float4 bv = *(const float4*)&ws[cur][kk][tx * 4];
            float a4[4] = {av.x, av.y, av.z, av.w};
            float b4[4] = {bv.x, bv.y, bv.z, bv.w};
#pragma unroll
            for (int i = 0; i < 4; ++i)
#pragma unroll
                for (int j = 0; j < 4; ++j)
                    acc[i][j] = fmaf(a4[i], b4[j], acc[i][j]);
        }
        if (kt < 3) {
            STS_TILE(cur ^ 1);
            __syncthreads();
        }
    }

    float* out = &g_part[z][g][0][0];
#pragma unroll
    for (int i = 0; i < 4; ++i) {
        int m = ty * 4 + i;
        float4 v = make_float4(acc[i][0], acc[i][1], acc[i][2], acc[i][3]);
        *(float4*)&out[(size_t)m * HID + n0 + tx * 4] = v;
    }
#undef LDG_TILE
#undef STS_TILE
}

// ---------------- kernel 2: gate pointwise + per-batch reduction -------------
__global__ void __launch_bounds__(256) pointwise_kernel(
    const float* __restrict__ nprev, const float* __restrict__ mprev_in,
    WPtrs wp, float* __restrict__ out_n, float* __restrict__ out_m)
{
    const int b   = blockIdx.x;
    const int tid = threadIdx.x;
    float local_nq = 0.0f;

#pragma unroll
    for (int t = 0; t < 4; ++t) {
        const int h = tid + t * 256;
        float s[6];
#pragma unroll
        for (int g = 0; g < 6; ++g) {
            float v = wp.b[g][h];
#pragma unroll
            for (int zz = 0; zz < SPLITK; ++zz) v += g_part[zz][g][b][h];
            s[g] = v;
        }
        const float it   = s[0];
        const float ftil = s[1];
        const float otil = s[2];
        const float qv   = s[3];
        const float kv   = s[4] * (1.0f / 32.0f);   // / sqrt(1024)
        const float vv   = s[5];

        const float ft   = 1.0f / (1.0f + expf(-ftil));
        // log(sigmoid(ftil)), numerically stable
        const float lgf  = (ftil >= 0.0f) ? -log1pf(expf(-ftil))
                                          : (ftil - log1pf(expf(ftil)));
        const float mp = mprev_in[(size_t)b * HID + h];
        const float mt = fmaxf(lgf + mp, it);
        const float ip = expf(it - mt);
        const float nt = ft * nprev[(size_t)b * HID + h] + ip * kv;

        out_n[(size_t)b * HID + h] = nt;
        out_m[(size_t)b * HID + h] = mt;
        g_f[b][h] = ft;
        g_a[b][h] = ip * vv;
        g_o[b][h] = 1.0f / (1.0f + expf(-otil));
        g_k[b][h] = kv;
        g_q[b][h] = qv;
        local_nq += nt * qv;
    }

    // block reduce local_nq (256 threads = 8 warps)
    __shared__ float red[8];
#pragma unroll
    for (int off = 16; off > 0; off >>= 1)
        local_nq += __shfl_xor_sync(0xFFFFFFFFu, local_nq, off);
    if ((tid & 31) == 0) red[tid >> 5] = local_nq;
    __syncthreads();
    if (tid < 8) {
        float v = red[tid];
#pragma unroll
        for (int off = 4; off > 0; off >>= 1)
            v += __shfl_xor_sync(0xFFu, v, off);
        if (tid == 0) g_nq[b] = v;
    }
}

// ---------------- kernel 3: fused fast-weight update + readout ---------------
// One warp per C row; 16 rows per block; k,q cached in smem per block.
__global__ void __launch_bounds__(512) update_kernel(
    const float* __restrict__ C, float* __restrict__ outC, float* __restrict__ outH)
{
    __shared__ float sk[HID];
    __shared__ float sq[HID];

    const int b  = blockIdx.x >> 6;          // 64 blocks per batch
    const int r0 = (blockIdx.x & 63) << 4;   // 16 rows per block

    for (int i = threadIdx.x; i < HID; i += 512) {
        sk[i] = g_k[b][i];
        sq[i] = g_q[b][i];
    }
    __syncthreads();

    const int w    = threadIdx.x >> 5;
    const int lane = threadIdx.x & 31;
    const int r    = r0 + w;

    const float f = g_f[b][r];
    const float a = g_a[b][r];

    const size_t base = ((size_t)b * HID + r) * HID;
    const float4* __restrict__ Crow = (const float4*)(C + base);
    float4* __restrict__ Orow       = (float4*)(outC + base);
    const float4* __restrict__ k4p  = (const float4*)sk;
    const float4* __restrict__ q4p  = (const float4*)sq;

    float acc = 0.0f;
#pragma unroll
    for (int t = 0; t < 8; ++t) {
        const int j  = lane + t * 32;        // float4 index, coalesced
        float4 c  = Crow[j];
        float4 k4 = k4p[j];
        float4 q4 = q4p[j];
        float4 ct;
        ct.x = fmaf(f, c.x, a * k4.x);
        ct.y = fmaf(f, c.y, a * k4.y);
        ct.z = fmaf(f, c.z, a * k4.z);
        ct.w = fmaf(f, c.w, a * k4.w);
        Orow[j] = ct;
        acc = fmaf(ct.x, q4.x, acc);
        acc = fmaf(ct.y, q4.y, acc);
        acc = fmaf(ct.z, q4.z, acc);
        acc = fmaf(ct.w, q4.w, acc);
    }
#pragma unroll
    for (int off = 16; off > 0; off >>= 1)
        acc += __shfl_xor_sync(0xFFFFFFFFu, acc, off);

    if (lane == 0) {
        const float div = fmaxf(fabsf(g_nq[b]), 1.0f);
        outH[(size_t)b * HID + r] = g_o[b][r] * acc / div;
    }
}

// ---------------- launch ------------------------------------------------------
extern "C" void kernel_launch(void* const* d_in, const int* in_sizes, int n_in,
                              void* d_out, int out_size)
{
    const float* x     = (const float*)d_in[0];
    const float* Cin   = (const float*)d_in[1];
    const float* nprev = (const float*)d_in[2];
    const float* mprev = (const float*)d_in[3];

    WPtrs wp;
    for (int g = 0; g < 6; ++g) {
        wp.W[g] = (const float*)d_in[4 + 2 * g];
        wp.b[g] = (const float*)d_in[5 + 2 * g];
    }

    float* out  = (float*)d_out;
    float* outH = out;                                       // (64,1024)
    float* outC = out + (size_t)BATCH * HID;                 // (64,1024,1024)
    float* outN = outC + (size_t)BATCH * HID * HID;          // (64,1024)
    float* outM = outN + (size_t)BATCH * HID;                // (64,1024)

    gemm6_kernel<<<dim3(16, 6, SPLITK), 256>>>(x, wp);
    pointwise_kernel<<<BATCH, 256>>>(nprev, mprev, wp, outN, outM);
    update_kernel<<<BATCH * (HID / 16), 512>>>(Cin, outC, outH);
}